// round 10
// baseline (speedup 1.0000x reference)
#include <cuda_runtime.h>
#include <cstdint>

#define B_ 32
#define L_ 2048
#define S_ 8
#define HALO 8
#define OUT_ROWS ((L_ - 1) * (S_ + 1) + 1)   // 18424
#define TILE_L 64
#define ROWS_T (TILE_L + HALO)               // 72
#define WT_STRIDE 66                          // padded: kills STS conflicts on transpose
#define THREADS 288                           // 9 warps
#define RG 8                                  // rows per GEMM thread (9 groups x 8 = 72)

// region A (phase 1): Wt[66*64]=4224 + Bt[64*64]=4096 + Fs[72*64]=4608 floats
// region B (phase 2): Ps[72*64] + Qs[72*64] = 9216 floats, ALIASED over region A
#define SMEM_FLOATS (WT_STRIDE * 64 + 64 * 64 + ROWS_T * 64)   // 12928
#define FUSED_SMEM (SMEM_FLOATS * sizeof(float))                // 51712 B

typedef unsigned long long u64;

__device__ __forceinline__ void fma2(u64& d, u64 a, u64 b) {
    asm("fma.rn.f32x2 %0, %1, %2, %0;" : "+l"(d) : "l"(a), "l"(b));
}
__device__ __forceinline__ u64 mul2(u64 a, u64 b) {
    u64 r;
    asm("mul.rn.f32x2 %0, %1, %2;" : "=l"(r) : "l"(a), "l"(b));
    return r;
}
__device__ __forceinline__ u64 splat2(float f) {
    u64 r;
    asm("mov.b64 %0, {%1, %1};" : "=l"(r) : "f"(f));
    return r;
}

// non_pad_mask dtype probe. lengths >= L/2 so mask[0,0], mask[0,1] are true.
// u8: [1,1,..] | i32: [1,0,0,0,..] | f32: [0,0,0x80,0x3f]
__device__ __forceinline__ int mask_kind(const unsigned char* m) {
    unsigned char b0 = m[0], b1 = m[1];
    if (b0 == 1 && b1 != 0) return 0;
    if (b0 == 1) return 1;
    return 2;
}

__global__ __launch_bounds__(THREADS) void fused_kernel(const float* __restrict__ times,
                                                        const float* __restrict__ F,
                                                        const void* __restrict__ maskp,
                                                        const float* __restrict__ usample,
                                                        const float* __restrict__ W,
                                                        const float* __restrict__ bias,
                                                        float* __restrict__ out) {
    extern __shared__ __align__(16) float smem[];
    float* Wt = smem;                          // [c][o], row stride 66
    float* Bt = smem + WT_STRIDE * 64;         // [c][o], stride 64
    float* Fs = Bt + 64 * 64;                  // 72 x 64
    // phase-2 aliases (valid only after the post-GEMM sync). Hold MASKED m_j*P, m_j*Q.
    float* Ps = smem;                          // 72 x 64
    float* Qs = smem + ROWS_T * 64;            // 72 x 64
    __shared__ float ts[ROWS_T + 1];
    __shared__ float vsf[ROWS_T + 1];
    __shared__ float us[S_];

    int tid = threadIdx.x;
    int b = blockIdx.y;
    const float* gF = F + (size_t)b * L_ * 64;

    if (tid < S_) us[tid] = usample[tid];

    float4 pf[4];   // register prefetch of next tile's F (1152 float4 / 288 = 4 each)

    for (int half = 0; half < 2; half++) {
        int tileStart = (blockIdx.x * 2 + half) * TILE_L;
        if (half) __syncthreads();   // phase-2 readers of previous tile done

        // ---- loads: W transpose (coalesced LDG, 2-way-max STS via pad), bias, F ----
        for (int i = tid; i < 4096; i += THREADS) {
            int o = i >> 6, c = i & 63;        // consecutive i -> coalesced W read
            Wt[c * WT_STRIDE + o] = W[i];
        }
        for (int i = tid; i < 1024; i += THREADS) {
            int o4 = (i & 15) * 4, c = i >> 4;
            *(float4*)&Bt[c * 64 + o4] = ((const float4*)bias)[i];
        }
        if (half == 0) {
            for (int i = tid; i < ROWS_T * 16; i += THREADS) {
                int rr = i >> 4, cc = i & 15;
                int gl = tileStart - HALO + rr;
                float4 f = make_float4(0.f, 0.f, 0.f, 0.f);
                if (gl >= 0) f = ((const float4*)(gF + (size_t)gl * 64))[cc];
                ((float4*)Fs)[i] = f;
            }
        } else {
#pragma unroll
            for (int k = 0; k < 4; k++)
                ((float4*)Fs)[tid + k * THREADS] = pf[k];
        }
        if (tid < ROWS_T + 1) {
            int kind = mask_kind((const unsigned char*)maskp);
            int gl = tileStart - HALO + tid;
            float t = 0.f, v = 0.f;
            if (gl >= 0 && gl < L_) {
                int mi = b * L_ + gl;
                t = times[mi];
                bool mv;
                if (kind == 0)      mv = ((const unsigned char*)maskp)[mi] != 0;
                else if (kind == 1) mv = ((const int*)maskp)[mi] != 0;
                else                mv = ((const float*)maskp)[mi] != 0.f;
                v = mv ? 1.f : 0.f;
            }
            ts[tid] = t;
            vsf[tid] = v;
        }
        __syncthreads();

        // ---- phase 1: GEMM. thread = (o-pair o2 = lane, 8-row group rg 0..8) ----
        int o2 = tid & 31;
        int rg = tid >> 5;          // warp-uniform -> Fs loads broadcast
        int row0 = rg * RG;

        u64 aP[RG], aQ[RG];
#pragma unroll
        for (int j = 0; j < RG; j++) { aP[j] = 0ull; aQ[j] = 0ull; }

#pragma unroll
        for (int c4 = 0; c4 < 16; c4++) {
            float4 fv[RG];
#pragma unroll
            for (int j = 0; j < RG; j++)
                fv[j] = *(const float4*)&Fs[(row0 + j) * 64 + c4 * 4];
#pragma unroll
            for (int cc = 0; cc < 4; cc++) {
                int c = c4 * 4 + cc;
                u64 w2 = *(const u64*)&Wt[c * WT_STRIDE + o2 * 2];
                u64 b2 = *(const u64*)&Bt[c * 64 + o2 * 2];
#pragma unroll
                for (int j = 0; j < RG; j++) {
                    u64 ff = splat2(((const float*)&fv[j])[cc]);
                    fma2(aP[j], ff, w2);
                    fma2(aQ[j], ff, b2);
                }
            }
        }
        __syncthreads();   // Wt/Bt/Fs reads complete -> safe to overwrite (alias)

        // writeback with mask folded in: Ps = m_j*P, Qs = m_j*Q
#pragma unroll
        for (int j = 0; j < RG; j++) {
            u64 mm = splat2(vsf[row0 + j]);
            *(u64*)&Ps[(row0 + j) * 64 + o2 * 2] = mul2(aP[j], mm);
            *(u64*)&Qs[(row0 + j) * 64 + o2 * 2] = mul2(aQ[j], mm);
        }

        // issue next tile's F loads now; they land during phase 2 below
        if (half == 0) {
            int t2 = tileStart + TILE_L;
#pragma unroll
            for (int k = 0; k < 4; k++) {
                int i = tid + k * THREADS;
                int rr = i >> 4, cc = i & 15;
                int gl = t2 - HALO + rr;       // always >= 56
                pf[k] = ((const float4*)(gF + (size_t)gl * 64))[cc];
            }
        }
        __syncthreads();

        // ---- phase 2: sliding-window combine ----
        // real[l] = m_l*(t_l*A + E),   A = sum_{j=l-8..l-1} mP_j,  E = sum (mQ_j - t_j*mP_j)
        // sim[l]  = m_l*(t_l*An + En), An/En = window advanced to j=l-7..l (8 taps)
        // sum_lin = m_l*An. 288 threads = 16 o4-lanes x 18 chunks (10x4 + 8x3 = 64 l's).
        {
            int o4 = (tid & 15) * 4;
            int chunk = tid >> 4;                       // 0..17
            int l0  = chunk < 10 ? chunk * 4 : 40 + (chunk - 10) * 3;
            int len = chunk < 10 ? 4 : 3;

            float4 A = make_float4(0.f, 0.f, 0.f, 0.f);
            float4 E = make_float4(0.f, 0.f, 0.f, 0.f);
#pragma unroll
            for (int i = 0; i < 8; i++) {      // init window j = l0-8..l0-1 (rows l0..l0+7)
                int r = l0 + i;
                float4 p = *(const float4*)&Ps[r * 64 + o4];
                float4 q = *(const float4*)&Qs[r * 64 + o4];
                float t = ts[r];
                A.x += p.x; A.y += p.y; A.z += p.z; A.w += p.w;
                E.x += fmaf(-t, p.x, q.x); E.y += fmaf(-t, p.y, q.y);
                E.z += fmaf(-t, p.z, q.z); E.w += fmaf(-t, p.w, q.w);
            }

#pragma unroll
            for (int i = 0; i < 4; i++) {
                if (i >= len) break;
                int ll = l0 + i;
                int l = tileStart + ll;
                float tl = ts[ll + HALO];
                float m  = vsf[ll + HALO];

                float4 pn = *(const float4*)&Ps[(ll + HALO) * 64 + o4];   // new tap j=l
                float4 qn = *(const float4*)&Qs[(ll + HALO) * 64 + o4];
                float4 po = *(const float4*)&Ps[ll * 64 + o4];            // old tap j=l-8
                float4 qo = *(const float4*)&Qs[ll * 64 + o4];
                float to = ts[ll];

                float4 An, En;
                An.x = A.x + pn.x - po.x; An.y = A.y + pn.y - po.y;
                An.z = A.z + pn.z - po.z; An.w = A.w + pn.w - po.w;
                En.x = fmaf(to, po.x, fmaf(-tl, pn.x, E.x + qn.x) - qo.x);
                En.y = fmaf(to, po.y, fmaf(-tl, pn.y, E.y + qn.y) - qo.y);
                En.z = fmaf(to, po.z, fmaf(-tl, pn.z, E.z + qn.z) - qo.z);
                En.w = fmaf(to, po.w, fmaf(-tl, pn.w, E.w + qn.w) - qo.w);

                float4 re, sb, sl;
                re.x = m * fmaf(tl, A.x, E.x);   re.y = m * fmaf(tl, A.y, E.y);
                re.z = m * fmaf(tl, A.z, E.z);   re.w = m * fmaf(tl, A.w, E.w);
                sb.x = m * fmaf(tl, An.x, En.x); sb.y = m * fmaf(tl, An.y, En.y);
                sb.z = m * fmaf(tl, An.z, En.z); sb.w = m * fmaf(tl, An.w, En.w);
                sl.x = m * An.x; sl.y = m * An.y; sl.z = m * An.z; sl.w = m * An.w;

                float* ob = out + ((size_t)b * OUT_ROWS + (size_t)l * 9) * 64 + o4;
                *(float4*)ob = re;

                if (l < L_ - 1) {
                    float udt = (m != 0.f && vsf[ll + HALO + 1] != 0.f)
                                    ? (ts[ll + HALO + 1] - tl) : 0.f;
#pragma unroll
                    for (int s = 0; s < S_; s++) {
                        float f = udt * us[s];
                        float4 v = make_float4(fmaf(f, sl.x, sb.x), fmaf(f, sl.y, sb.y),
                                               fmaf(f, sl.z, sb.z), fmaf(f, sl.w, sb.w));
                        *(float4*)(ob + (s + 1) * 64) = v;
                    }
                }

                A = An;
                E = En;
            }
        }
    }
}

extern "C" void kernel_launch(void* const* d_in, const int* in_sizes, int n_in,
                              void* d_out, int out_size) {
    const float* times    = (const float*)d_in[0];
    const float* features = (const float*)d_in[1];
    const void*  mask     = d_in[2];
    const float* usample  = (const float*)d_in[3];
    const float* W        = (const float*)d_in[4];
    const float* bias     = (const float*)d_in[5];
    float* out = (float*)d_out;

    cudaFuncSetAttribute(fused_kernel, cudaFuncAttributeMaxDynamicSharedMemorySize,
                         (int)FUSED_SMEM);
    dim3 g(L_ / TILE_L / 2, B_);   // (16, 32): each block does 2 tiles
    fused_kernel<<<g, THREADS, FUSED_SMEM>>>(times, features, mask, usample, W, bias, out);
}

// round 11
// speedup vs baseline: 1.2364x; 1.2364x over previous
#include <cuda_runtime.h>
#include <cstdint>

#define B_ 32
#define L_ 2048
#define S_ 8
#define HALO 8
#define OUT_ROWS ((L_ - 1) * (S_ + 1) + 1)   // 18424
#define TILE_L 64
#define ROWS_T (TILE_L + HALO)               // 72
#define WT_STRIDE 66                          // padded: kills 32-way STS conflicts

// region A (phase 1): Wt[66*64] + Bt[64*64] + Fs[72*64] = 12928 floats
// region B (phase 2): Ps[72*64] + Qs[72*64] = 9216 floats, ALIASED over region A
#define SMEM_FLOATS (WT_STRIDE * 64 + 64 * 64 + ROWS_T * 64)
#define FUSED_SMEM (SMEM_FLOATS * sizeof(float))   // 51712 B -> 4 blocks/SM

typedef unsigned long long u64;

__device__ __forceinline__ void fma2(u64& d, u64 a, u64 b) {
    asm("fma.rn.f32x2 %0, %1, %2, %0;" : "+l"(d) : "l"(a), "l"(b));
}
__device__ __forceinline__ u64 mul2(u64 a, u64 b) {
    u64 r;
    asm("mul.rn.f32x2 %0, %1, %2;" : "=l"(r) : "l"(a), "l"(b));
    return r;
}
__device__ __forceinline__ u64 splat2(float f) {
    u64 r;
    asm("mov.b64 %0, {%1, %1};" : "=l"(r) : "f"(f));
    return r;
}

// non_pad_mask dtype probe. lengths >= L/2 so mask[0,0], mask[0,1] are true.
// u8: [1,1,..] | i32: [1,0,0,0,..] | f32: [0,0,0x80,0x3f]
__device__ __forceinline__ int mask_kind(const unsigned char* m) {
    unsigned char b0 = m[0], b1 = m[1];
    if (b0 == 1 && b1 != 0) return 0;
    if (b0 == 1) return 1;
    return 2;
}

__global__ __launch_bounds__(256, 4) void fused_kernel(const float* __restrict__ times,
                                                       const float* __restrict__ F,
                                                       const void* __restrict__ maskp,
                                                       const float* __restrict__ usample,
                                                       const float* __restrict__ W,
                                                       const float* __restrict__ bias,
                                                       float* __restrict__ out) {
    extern __shared__ __align__(16) float smem[];
    float* Wt = smem;                          // [c][o], row stride 66
    float* Bt = smem + WT_STRIDE * 64;         // [c][o], stride 64
    float* Fs = Bt + 64 * 64;                  // 72 x 64
    // phase-2 aliases (valid only after the post-GEMM sync). Hold MASKED m_j*P, m_j*Q.
    float* Ps = smem;                          // 72 x 64
    float* Qs = smem + ROWS_T * 64;            // 72 x 64
    __shared__ float ts[ROWS_T + 1];
    __shared__ float vsf[ROWS_T + 1];          // mask as float 0/1
    __shared__ float us[S_];

    int tid = threadIdx.x;
    int b = blockIdx.y;
    int tileStart = blockIdx.x * TILE_L;

    // ---- loads: W (coalesced LDG, padded STS), bias (copy), F halo tile, scalars ----
    for (int i = tid; i < 4096; i += 256) {
        int o = i >> 6, c = i & 63;
        Wt[c * WT_STRIDE + o] = W[i];
    }
    for (int i = tid; i < 1024; i += 256) {
        int o4 = (i & 15) * 4, c = i >> 4;
        *(float4*)&Bt[c * 64 + o4] = ((const float4*)bias)[i];
    }
    const float* gF = F + (size_t)b * L_ * 64;
    for (int i = tid; i < ROWS_T * 16; i += 256) {
        int rr = i >> 4, cc = i & 15;
        int gl = tileStart - HALO + rr;
        float4 f = make_float4(0.f, 0.f, 0.f, 0.f);
        if (gl >= 0) f = ((const float4*)(gF + (size_t)gl * 64))[cc];
        ((float4*)Fs)[i] = f;
    }
    if (tid < ROWS_T + 1) {
        int kind = mask_kind((const unsigned char*)maskp);
        int gl = tileStart - HALO + tid;
        float t = 0.f, v = 0.f;
        if (gl >= 0 && gl < L_) {
            int mi = b * L_ + gl;
            t = times[mi];
            bool mv;
            if (kind == 0)      mv = ((const unsigned char*)maskp)[mi] != 0;
            else if (kind == 1) mv = ((const int*)maskp)[mi] != 0;
            else                mv = ((const float*)maskp)[mi] != 0.f;
            v = mv ? 1.f : 0.f;
        }
        ts[tid] = t;
        vsf[tid] = v;
    }
    if (tid < S_) us[tid] = usample[tid];
    __syncthreads();

    // ---- phase 1: GEMM tile into registers. thread = (o-pair o2, 9-row group rg) ----
    // Channel-pair inner structure: tiny live set (36 acc + 8 wb + 2 fv regs).
    int o2 = tid & 31;          // o = 2*o2, 2*o2+1
    int rg = tid >> 5;          // warp-uniform -> Fs loads broadcast
    int row0 = rg * 9;

    u64 aP[9], aQ[9];
#pragma unroll
    for (int j = 0; j < 9; j++) { aP[j] = 0ull; aQ[j] = 0ull; }

#pragma unroll
    for (int c4 = 0; c4 < 16; c4++) {
#pragma unroll
        for (int h = 0; h < 2; h++) {
            int c0 = c4 * 4 + h * 2;
            u64 w20 = *(const u64*)&Wt[c0 * WT_STRIDE + o2 * 2];
            u64 w21 = *(const u64*)&Wt[(c0 + 1) * WT_STRIDE + o2 * 2];
            u64 b20 = *(const u64*)&Bt[c0 * 64 + o2 * 2];
            u64 b21 = *(const u64*)&Bt[(c0 + 1) * 64 + o2 * 2];
#pragma unroll
            for (int j = 0; j < 9; j++) {
                float2 fv = *(const float2*)&Fs[(row0 + j) * 64 + c0];  // broadcast LDS.64
                u64 f0 = splat2(fv.x);
                u64 f1 = splat2(fv.y);
                fma2(aP[j], f0, w20);
                fma2(aQ[j], f0, b20);
                fma2(aP[j], f1, w21);
                fma2(aQ[j], f1, b21);
            }
        }
    }
    __syncthreads();   // all Wt/Bt/Fs reads complete -> safe to overwrite (alias)

    // writeback with mask folded in: Ps = m_j*P, Qs = m_j*Q
#pragma unroll
    for (int j = 0; j < 9; j++) {
        u64 mm = splat2(vsf[row0 + j]);
        *(u64*)&Ps[(row0 + j) * 64 + o2 * 2] = mul2(aP[j], mm);
        *(u64*)&Qs[(row0 + j) * 64 + o2 * 2] = mul2(aQ[j], mm);
    }
    __syncthreads();

    // ---- phase 2: sliding-window combine ----
    // real[l] = m_l*(t_l*A + E),   A = sum_{j=l-8..l-1} mP_j,  E = sum (mQ_j - t_j*mP_j)
    // sim[l]  = m_l*(t_l*An + En), An/En = window advanced to j=l-7..l (8 taps)
    // sum_lin = m_l*An.  Carry (An,En) into the next l.
    {
        int o4 = (tid & 15) * 4;
        int l0 = (tid >> 4) * 4;   // local l of chunk start

        float4 A = make_float4(0.f, 0.f, 0.f, 0.f);
        float4 E = make_float4(0.f, 0.f, 0.f, 0.f);
#pragma unroll
        for (int i = 0; i < 8; i++) {          // init window j = l0-8 .. l0-1 (rows l0..l0+7)
            int r = l0 + i;
            float4 p = *(const float4*)&Ps[r * 64 + o4];
            float4 q = *(const float4*)&Qs[r * 64 + o4];
            float t = ts[r];
            A.x += p.x; A.y += p.y; A.z += p.z; A.w += p.w;
            E.x += fmaf(-t, p.x, q.x); E.y += fmaf(-t, p.y, q.y);
            E.z += fmaf(-t, p.z, q.z); E.w += fmaf(-t, p.w, q.w);
        }

#pragma unroll
        for (int i = 0; i < 4; i++) {
            int ll = l0 + i;
            int l = tileStart + ll;
            float tl = ts[ll + HALO];
            float m  = vsf[ll + HALO];

            float4 pn = *(const float4*)&Ps[(ll + HALO) * 64 + o4];   // new tap j=l
            float4 qn = *(const float4*)&Qs[(ll + HALO) * 64 + o4];
            float4 po = *(const float4*)&Ps[ll * 64 + o4];            // old tap j=l-8
            float4 qo = *(const float4*)&Qs[ll * 64 + o4];
            float to = ts[ll];

            // advanced 8-tap window j = l-7..l  (add new, drop old)
            float4 An, En;
            An.x = A.x + pn.x - po.x; An.y = A.y + pn.y - po.y;
            An.z = A.z + pn.z - po.z; An.w = A.w + pn.w - po.w;
            En.x = fmaf(to, po.x, fmaf(-tl, pn.x, E.x + qn.x) - qo.x);
            En.y = fmaf(to, po.y, fmaf(-tl, pn.y, E.y + qn.y) - qo.y);
            En.z = fmaf(to, po.z, fmaf(-tl, pn.z, E.z + qn.z) - qo.z);
            En.w = fmaf(to, po.w, fmaf(-tl, pn.w, E.w + qn.w) - qo.w);

            float4 re, sb, sl;
            re.x = m * fmaf(tl, A.x, E.x);   re.y = m * fmaf(tl, A.y, E.y);
            re.z = m * fmaf(tl, A.z, E.z);   re.w = m * fmaf(tl, A.w, E.w);
            sb.x = m * fmaf(tl, An.x, En.x); sb.y = m * fmaf(tl, An.y, En.y);
            sb.z = m * fmaf(tl, An.z, En.z); sb.w = m * fmaf(tl, An.w, En.w);
            sl.x = m * An.x; sl.y = m * An.y; sl.z = m * An.z; sl.w = m * An.w;

            float* ob = out + ((size_t)b * OUT_ROWS + (size_t)l * 9) * 64 + o4;
            *(float4*)ob = re;

            if (l < L_ - 1) {
                float udt = (m != 0.f && vsf[ll + HALO + 1] != 0.f)
                                ? (ts[ll + HALO + 1] - tl) : 0.f;
#pragma unroll
                for (int s = 0; s < S_; s++) {
                    float f = udt * us[s];
                    float4 v = make_float4(fmaf(f, sl.x, sb.x), fmaf(f, sl.y, sb.y),
                                           fmaf(f, sl.z, sb.z), fmaf(f, sl.w, sb.w));
                    *(float4*)(ob + (s + 1) * 64) = v;
                }
            }

            A = An;   // window for real[l+1] is exactly j = l-7..l
            E = En;
        }
    }
}

extern "C" void kernel_launch(void* const* d_in, const int* in_sizes, int n_in,
                              void* d_out, int out_size) {
    const float* times    = (const float*)d_in[0];
    const float* features = (const float*)d_in[1];
    const void*  mask     = d_in[2];
    const float* usample  = (const float*)d_in[3];
    const float* W        = (const float*)d_in[4];
    const float* bias     = (const float*)d_in[5];
    float* out = (float*)d_out;

    cudaFuncSetAttribute(fused_kernel, cudaFuncAttributeMaxDynamicSharedMemorySize,
                         (int)FUSED_SMEM);
    dim3 g(L_ / TILE_L, B_);
    fused_kernel<<<g, 256, FUSED_SMEM>>>(times, features, mask, usample, W, bias, out);
}

// round 12
// speedup vs baseline: 1.2727x; 1.0294x over previous
#include <cuda_runtime.h>
#include <cstdint>

#define B_ 32
#define L_ 2048
#define S_ 8
#define HALO 8
#define OUT_ROWS ((L_ - 1) * (S_ + 1) + 1)   // 18424
#define TILE_L 64
#define ROWS_T (TILE_L + HALO)               // 72
#define WT_STRIDE 66                          // padded: kills 32-way STS conflicts
#define CHUNK_L 16                            // l's per staged store chunk
#define STAGE_FLOATS (CHUNK_L * 9 * 64)       // 9216 floats = 36864 B

// Region A (phase 1): Wt[66*64]=4224 + Bt[4096] + Fs[72*64]=4608 = 12928 floats
// Region B (phase 2): Ps[4608] + Qs[4608] = 9216 floats + Stage[9216]
// Stage overlaps tail of region A (Fs) — written only after GEMM reads complete.
#define SMEM_FLOATS (9216 + STAGE_FLOATS)     // 18432 floats
#define FUSED_SMEM (SMEM_FLOATS * sizeof(float))   // 73728 B -> 3 blocks/SM

typedef unsigned long long u64;

__device__ __forceinline__ void fma2(u64& d, u64 a, u64 b) {
    asm("fma.rn.f32x2 %0, %1, %2, %0;" : "+l"(d) : "l"(a), "l"(b));
}
__device__ __forceinline__ u64 mul2(u64 a, u64 b) {
    u64 r;
    asm("mul.rn.f32x2 %0, %1, %2;" : "=l"(r) : "l"(a), "l"(b));
    return r;
}
__device__ __forceinline__ u64 splat2(float f) {
    u64 r;
    asm("mov.b64 %0, {%1, %1};" : "=l"(r) : "f"(f));
    return r;
}

// non_pad_mask dtype probe. lengths >= L/2 so mask[0,0], mask[0,1] are true.
// u8: [1,1,..] | i32: [1,0,0,0,..] | f32: [0,0,0x80,0x3f]
__device__ __forceinline__ int mask_kind(const unsigned char* m) {
    unsigned char b0 = m[0], b1 = m[1];
    if (b0 == 1 && b1 != 0) return 0;
    if (b0 == 1) return 1;
    return 2;
}

__global__ __launch_bounds__(256, 3) void fused_kernel(const float* __restrict__ times,
                                                       const float* __restrict__ F,
                                                       const void* __restrict__ maskp,
                                                       const float* __restrict__ usample,
                                                       const float* __restrict__ W,
                                                       const float* __restrict__ bias,
                                                       float* __restrict__ out) {
    extern __shared__ __align__(16) float smem[];
    float* Wt = smem;                          // [c][o], row stride 66 (phase 1)
    float* Bt = smem + WT_STRIDE * 64;         // [c][o], stride 64     (phase 1)
    float* Fs = Bt + 64 * 64;                  //                       (phase 1)
    float* Ps = smem;                          // 72 x 64 MASKED m*P    (phase 2)
    float* Qs = smem + ROWS_T * 64;            // 72 x 64 MASKED m*Q    (phase 2)
    float* Stage = smem + 2 * ROWS_T * 64;     // 16 l x 9 rows x 64    (phase 2)
    __shared__ float ts[ROWS_T + 1];
    __shared__ float vsf[ROWS_T + 1];
    __shared__ float us[S_];

    int tid = threadIdx.x;
    int b = blockIdx.y;
    int tileStart = blockIdx.x * TILE_L;

    // ---- loads: W (coalesced LDG, padded STS), bias, F halo tile, scalars ----
    for (int i = tid; i < 4096; i += 256) {
        int o = i >> 6, c = i & 63;
        Wt[c * WT_STRIDE + o] = W[i];
    }
    for (int i = tid; i < 1024; i += 256) {
        int o4 = (i & 15) * 4, c = i >> 4;
        *(float4*)&Bt[c * 64 + o4] = ((const float4*)bias)[i];
    }
    const float* gF = F + (size_t)b * L_ * 64;
    for (int i = tid; i < ROWS_T * 16; i += 256) {
        int rr = i >> 4, cc = i & 15;
        int gl = tileStart - HALO + rr;
        float4 f = make_float4(0.f, 0.f, 0.f, 0.f);
        if (gl >= 0) f = ((const float4*)(gF + (size_t)gl * 64))[cc];
        ((float4*)Fs)[i] = f;
    }
    if (tid < ROWS_T + 1) {
        int kind = mask_kind((const unsigned char*)maskp);
        int gl = tileStart - HALO + tid;
        float t = 0.f, v = 0.f;
        if (gl >= 0 && gl < L_) {
            int mi = b * L_ + gl;
            t = times[mi];
            bool mv;
            if (kind == 0)      mv = ((const unsigned char*)maskp)[mi] != 0;
            else if (kind == 1) mv = ((const int*)maskp)[mi] != 0;
            else                mv = ((const float*)maskp)[mi] != 0.f;
            v = mv ? 1.f : 0.f;
        }
        ts[tid] = t;
        vsf[tid] = v;
    }
    if (tid < S_) us[tid] = usample[tid];
    __syncthreads();

    // ---- phase 1: GEMM (R6 structure — regs ~80, no spills) ----
    int o2 = tid & 31;
    int rg = tid >> 5;
    int row0 = rg * 9;

    u64 aP[9], aQ[9];
#pragma unroll
    for (int j = 0; j < 9; j++) { aP[j] = 0ull; aQ[j] = 0ull; }

#pragma unroll
    for (int c4 = 0; c4 < 16; c4++) {
        float4 fv[9];
#pragma unroll
        for (int j = 0; j < 9; j++)
            fv[j] = *(const float4*)&Fs[(row0 + j) * 64 + c4 * 4];
#pragma unroll
        for (int cc = 0; cc < 4; cc++) {
            int c = c4 * 4 + cc;
            u64 w2 = *(const u64*)&Wt[c * WT_STRIDE + o2 * 2];
            u64 b2 = *(const u64*)&Bt[c * 64 + o2 * 2];
#pragma unroll
            for (int j = 0; j < 9; j++) {
                u64 ff = splat2(((const float*)&fv[j])[cc]);
                fma2(aP[j], ff, w2);
                fma2(aQ[j], ff, b2);
            }
        }
    }
    __syncthreads();   // Wt/Bt/Fs reads complete -> safe to overwrite (alias)

    // writeback with mask folded in: Ps = m_j*P, Qs = m_j*Q
#pragma unroll
    for (int j = 0; j < 9; j++) {
        u64 mm = splat2(vsf[row0 + j]);
        *(u64*)&Ps[(row0 + j) * 64 + o2 * 2] = mul2(aP[j], mm);
        *(u64*)&Qs[(row0 + j) * 64 + o2 * 2] = mul2(aQ[j], mm);
    }
    __syncthreads();

    // ---- phase 2: 9-tap direct combine, staged stores + bulk copy ----
    // With masked mP/mQ: tap_k = (tl - t_j)*mP_j + mQ_j.
    // real = m_l * sum_{k=0..7}, simbase = m_l * sum_{k=1..8}, sum_lin = m_l * sum mP (k=1..8).
    uint32_t stage_u32;
    asm("{ .reg .u64 t; cvta.to.shared.u64 t, %1; cvt.u32.u64 %0, t; }"
        : "=r"(stage_u32) : "l"((void*)Stage));

    int o4 = (tid & 15) * 4;
    int lsub = tid >> 4;       // 0..15

    for (int ck = 0; ck < 4; ck++) {
        int ll = ck * CHUNK_L + lsub;
        int l = tileStart + ll;
        float tl = ts[ll + HALO];
        float ml = vsf[ll + HALO];

        float4 re = make_float4(0.f, 0.f, 0.f, 0.f);
        float4 sb = re, sl = re;

#pragma unroll
        for (int k = 0; k < 9; k++) {
            int si = ll + k;
            float dt = tl - ts[si];
            const float4 p = *(const float4*)&Ps[si * 64 + o4];
            const float4 q = *(const float4*)&Qs[si * 64 + o4];
            float tx = fmaf(dt, p.x, q.x);
            float ty = fmaf(dt, p.y, q.y);
            float tz = fmaf(dt, p.z, q.z);
            float tw = fmaf(dt, p.w, q.w);
            if (k < 8) { re.x += tx; re.y += ty; re.z += tz; re.w += tw; }
            if (k >= 1) {
                sb.x += tx; sb.y += ty; sb.z += tz; sb.w += tw;
                sl.x += p.x; sl.y += p.y; sl.z += p.z; sl.w += p.w;
            }
        }
        re.x *= ml; re.y *= ml; re.z *= ml; re.w *= ml;
        sb.x *= ml; sb.y *= ml; sb.z *= ml; sb.w *= ml;
        sl.x *= ml; sl.y *= ml; sl.z *= ml; sl.w *= ml;

        // wait until previous chunk's bulk copy has read the staging buffer
        if (ck > 0 && tid == 0)
            asm volatile("cp.async.bulk.wait_group.read 0;" ::: "memory");
        __syncthreads();

        float* srow = Stage + (lsub * 9) * 64 + o4;
        *(float4*)srow = re;
        if (l < L_ - 1) {
            float udt = (ml != 0.f && vsf[ll + HALO + 1] != 0.f)
                            ? (ts[ll + HALO + 1] - tl) : 0.f;
#pragma unroll
            for (int s = 0; s < S_; s++) {
                float f = udt * us[s];
                float4 v = make_float4(fmaf(f, sl.x, sb.x), fmaf(f, sl.y, sb.y),
                                       fmaf(f, sl.z, sb.z), fmaf(f, sl.w, sb.w));
                *(float4*)(srow + (s + 1) * 64) = v;
            }
        }
        __syncthreads();

        if (tid == 0) {
            // bytes: full chunk = 16*9*256; chunk containing l=2047 has only the
            // real row for its last l -> (15*9+1)*256.
            int lastl = tileStart + ck * CHUNK_L + CHUNK_L - 1;
            unsigned bytes = (lastl == L_ - 1) ? (15 * 9 + 1) * 256u
                                               : CHUNK_L * 9 * 256u;
            const float* gdst = out + ((size_t)b * OUT_ROWS
                                       + (size_t)(tileStart + ck * CHUNK_L) * 9) * 64;
            asm volatile("fence.proxy.async.shared::cta;" ::: "memory");
            asm volatile("cp.async.bulk.global.shared::cta.bulk_group [%0], [%1], %2;"
                         :: "l"(gdst), "r"(stage_u32), "r"(bytes) : "memory");
            asm volatile("cp.async.bulk.commit_group;" ::: "memory");
        }
    }

    if (tid == 0)
        asm volatile("cp.async.bulk.wait_group 0;" ::: "memory");
}

extern "C" void kernel_launch(void* const* d_in, const int* in_sizes, int n_in,
                              void* d_out, int out_size) {
    const float* times    = (const float*)d_in[0];
    const float* features = (const float*)d_in[1];
    const void*  mask     = d_in[2];
    const float* usample  = (const float*)d_in[3];
    const float* W        = (const float*)d_in[4];
    const float* bias     = (const float*)d_in[5];
    float* out = (float*)d_out;

    cudaFuncSetAttribute(fused_kernel, cudaFuncAttributeMaxDynamicSharedMemorySize,
                         (int)FUSED_SMEM);
    dim3 g(L_ / TILE_L, B_);
    fused_kernel<<<g, 256, FUSED_SMEM>>>(times, features, mask, usample, W, bias, out);
}

// round 13
// speedup vs baseline: 1.3125x; 1.0313x over previous
#include <cuda_runtime.h>
#include <cstdint>

#define B_ 32
#define L_ 2048
#define S_ 8
#define HALO 8
#define OUT_ROWS ((L_ - 1) * (S_ + 1) + 1)   // 18424
#define TILE_L 64
#define ROWS_T (TILE_L + HALO)               // 72
#define WT_STRIDE 66                          // padded: kills 32-way STS conflicts
#define THREADS 512

// region A (phase 1): Wt[66*64] + Bt[64*64] + Fs[72*64] = 12928 floats
// region B (phase 2): Ps[72*64] + Qs[72*64] = 9216 floats, ALIASED over region A
#define SMEM_FLOATS (WT_STRIDE * 64 + 64 * 64 + ROWS_T * 64)
#define FUSED_SMEM (SMEM_FLOATS * sizeof(float))   // 51712 B -> 2 blocks/SM (103 KB)

typedef unsigned long long u64;

__device__ __forceinline__ void fma2(u64& d, u64 a, u64 b) {
    asm("fma.rn.f32x2 %0, %1, %2, %0;" : "+l"(d) : "l"(a), "l"(b));
}
__device__ __forceinline__ u64 mul2(u64 a, u64 b) {
    u64 r;
    asm("mul.rn.f32x2 %0, %1, %2;" : "=l"(r) : "l"(a), "l"(b));
    return r;
}
__device__ __forceinline__ u64 splat2(float f) {
    u64 r;
    asm("mov.b64 %0, {%1, %1};" : "=l"(r) : "f"(f));
    return r;
}

// non_pad_mask dtype probe. lengths >= L/2 so mask[0,0], mask[0,1] are true.
// u8: [1,1,..] | i32: [1,0,0,0,..] | f32: [0,0,0x80,0x3f]
__device__ __forceinline__ int mask_kind(const unsigned char* m) {
    unsigned char b0 = m[0], b1 = m[1];
    if (b0 == 1 && b1 != 0) return 0;
    if (b0 == 1) return 1;
    return 2;
}

__global__ __launch_bounds__(THREADS, 2) void fused_kernel(const float* __restrict__ times,
                                                           const float* __restrict__ F,
                                                           const void* __restrict__ maskp,
                                                           const float* __restrict__ usample,
                                                           const float* __restrict__ W,
                                                           const float* __restrict__ bias,
                                                           float* __restrict__ out) {
    extern __shared__ __align__(16) float smem[];
    float* Wt = smem;                          // [c][o], row stride 66 (phase 1)
    float* Bt = smem + WT_STRIDE * 64;         // [c][o], stride 64     (phase 1)
    float* Fs = Bt + 64 * 64;                  // 72 x 64               (phase 1)
    // phase-2 aliases (valid only after the post-GEMM sync). Hold MASKED m_j*P, m_j*Q.
    float* Ps = smem;                          // 72 x 64
    float* Qs = smem + ROWS_T * 64;            // 72 x 64
    __shared__ float ts[ROWS_T + 1];
    __shared__ float vsf[ROWS_T + 1];          // mask as float 0/1
    __shared__ float us[S_];

    int tid = threadIdx.x;
    int b = blockIdx.y;
    int tileStart = blockIdx.x * TILE_L;

    // ---- loads: W (coalesced LDG, padded STS), bias (copy), F halo tile, scalars ----
    for (int i = tid; i < 4096; i += THREADS) {
        int o = i >> 6, c = i & 63;
        Wt[c * WT_STRIDE + o] = W[i];
    }
    for (int i = tid; i < 1024; i += THREADS) {
        int o4 = (i & 15) * 4, c = i >> 4;
        *(float4*)&Bt[c * 64 + o4] = ((const float4*)bias)[i];
    }
    const float* gF = F + (size_t)b * L_ * 64;
    for (int i = tid; i < ROWS_T * 16; i += THREADS) {
        int rr = i >> 4, cc = i & 15;
        int gl = tileStart - HALO + rr;
        float4 f = make_float4(0.f, 0.f, 0.f, 0.f);
        if (gl >= 0) f = ((const float4*)(gF + (size_t)gl * 64))[cc];
        ((float4*)Fs)[i] = f;
    }
    if (tid < ROWS_T + 1) {
        int kind = mask_kind((const unsigned char*)maskp);
        int gl = tileStart - HALO + tid;
        float t = 0.f, v = 0.f;
        if (gl >= 0 && gl < L_) {
            int mi = b * L_ + gl;
            t = times[mi];
            bool mv;
            if (kind == 0)      mv = ((const unsigned char*)maskp)[mi] != 0;
            else if (kind == 1) mv = ((const int*)maskp)[mi] != 0;
            else                mv = ((const float*)maskp)[mi] != 0.f;
            v = mv ? 1.f : 0.f;
        }
        ts[tid] = t;
        vsf[tid] = v;
    }
    if (tid < S_) us[tid] = usample[tid];
    __syncthreads();

    // ---- phase 1: GEMM. 16 warps: warps 0-7 compute P, warps 8-15 compute Q.
    // thread = (o-pair o2 = lane, 9-row group rg = wid&7). 9 u64 accumulators.
    int lane = tid & 31;
    int wid = tid >> 5;
    int isP = wid < 8;
    int rg = wid & 7;
    int row0 = rg * 9;
    int o2 = lane;

    const float* Mat = isP ? Wt : Bt;
    int mstride = isP ? WT_STRIDE : 64;
    float* Dst = isP ? Ps : Qs;

    u64 acc[9];
#pragma unroll
    for (int j = 0; j < 9; j++) acc[j] = 0ull;

#pragma unroll
    for (int c4 = 0; c4 < 16; c4++) {
        u64 m2[4];
#pragma unroll
        for (int cc = 0; cc < 4; cc++)
            m2[cc] = *(const u64*)&Mat[(c4 * 4 + cc) * mstride + o2 * 2];
#pragma unroll
        for (int j = 0; j < 9; j++) {
            float4 fv = *(const float4*)&Fs[(row0 + j) * 64 + c4 * 4];  // warp broadcast
            fma2(acc[j], splat2(fv.x), m2[0]);
            fma2(acc[j], splat2(fv.y), m2[1]);
            fma2(acc[j], splat2(fv.z), m2[2]);
            fma2(acc[j], splat2(fv.w), m2[3]);
        }
    }
    __syncthreads();   // all Wt/Bt/Fs reads complete -> safe to overwrite (alias)

    // writeback with mask folded in: Ps = m_j*P, Qs = m_j*Q
#pragma unroll
    for (int j = 0; j < 9; j++) {
        u64 mm = splat2(vsf[row0 + j]);
        *(u64*)&Dst[(row0 + j) * 64 + o2 * 2] = mul2(acc[j], mm);
    }
    __syncthreads();

    // ---- phase 2: sliding-window combine ----
    // real[l] = m_l*(t_l*A + E),   A = sum_{j=l-8..l-1} mP_j,  E = sum (mQ_j - t_j*mP_j)
    // sim[l]  = m_l*(t_l*An + En), An/En = window advanced to j=l-7..l (8 taps)
    // sum_lin = m_l*An.  512 threads = 16 o4-lanes x 32 chunks of 2 l's.
    {
        int o4 = (tid & 15) * 4;
        int l0 = (tid >> 4) * 2;   // local l of chunk start (0..62)

        float4 A = make_float4(0.f, 0.f, 0.f, 0.f);
        float4 E = make_float4(0.f, 0.f, 0.f, 0.f);
#pragma unroll
        for (int i = 0; i < 8; i++) {          // init window j = l0-8 .. l0-1 (rows l0..l0+7)
            int r = l0 + i;
            float4 p = *(const float4*)&Ps[r * 64 + o4];
            float4 q = *(const float4*)&Qs[r * 64 + o4];
            float t = ts[r];
            A.x += p.x; A.y += p.y; A.z += p.z; A.w += p.w;
            E.x += fmaf(-t, p.x, q.x); E.y += fmaf(-t, p.y, q.y);
            E.z += fmaf(-t, p.z, q.z); E.w += fmaf(-t, p.w, q.w);
        }

#pragma unroll
        for (int i = 0; i < 2; i++) {
            int ll = l0 + i;
            int l = tileStart + ll;
            float tl = ts[ll + HALO];
            float m  = vsf[ll + HALO];

            float4 pn = *(const float4*)&Ps[(ll + HALO) * 64 + o4];   // new tap j=l
            float4 qn = *(const float4*)&Qs[(ll + HALO) * 64 + o4];
            float4 po = *(const float4*)&Ps[ll * 64 + o4];            // old tap j=l-8
            float4 qo = *(const float4*)&Qs[ll * 64 + o4];
            float to = ts[ll];

            // advanced 8-tap window j = l-7..l  (add new, drop old)
            float4 An, En;
            An.x = A.x + pn.x - po.x; An.y = A.y + pn.y - po.y;
            An.z = A.z + pn.z - po.z; An.w = A.w + pn.w - po.w;
            En.x = fmaf(to, po.x, fmaf(-tl, pn.x, E.x + qn.x) - qo.x);
            En.y = fmaf(to, po.y, fmaf(-tl, pn.y, E.y + qn.y) - qo.y);
            En.z = fmaf(to, po.z, fmaf(-tl, pn.z, E.z + qn.z) - qo.z);
            En.w = fmaf(to, po.w, fmaf(-tl, pn.w, E.w + qn.w) - qo.w);

            float4 re, sb, sl;
            re.x = m * fmaf(tl, A.x, E.x);   re.y = m * fmaf(tl, A.y, E.y);
            re.z = m * fmaf(tl, A.z, E.z);   re.w = m * fmaf(tl, A.w, E.w);
            sb.x = m * fmaf(tl, An.x, En.x); sb.y = m * fmaf(tl, An.y, En.y);
            sb.z = m * fmaf(tl, An.z, En.z); sb.w = m * fmaf(tl, An.w, En.w);
            sl.x = m * An.x; sl.y = m * An.y; sl.z = m * An.z; sl.w = m * An.w;

            float* ob = out + ((size_t)b * OUT_ROWS + (size_t)l * 9) * 64 + o4;
            *(float4*)ob = re;

            if (l < L_ - 1) {
                float udt = (m != 0.f && vsf[ll + HALO + 1] != 0.f)
                                ? (ts[ll + HALO + 1] - tl) : 0.f;
#pragma unroll
                for (int s = 0; s < S_; s++) {
                    float f = udt * us[s];
                    float4 v = make_float4(fmaf(f, sl.x, sb.x), fmaf(f, sl.y, sb.y),
                                           fmaf(f, sl.z, sb.z), fmaf(f, sl.w, sb.w));
                    *(float4*)(ob + (s + 1) * 64) = v;
                }
            }

            A = An;   // window for real[l+1] is exactly j = l-7..l
            E = En;
        }
    }
}

extern "C" void kernel_launch(void* const* d_in, const int* in_sizes, int n_in,
                              void* d_out, int out_size) {
    const float* times    = (const float*)d_in[0];
    const float* features = (const float*)d_in[1];
    const void*  mask     = d_in[2];
    const float* usample  = (const float*)d_in[3];
    const float* W        = (const float*)d_in[4];
    const float* bias     = (const float*)d_in[5];
    float* out = (float*)d_out;

    cudaFuncSetAttribute(fused_kernel, cudaFuncAttributeMaxDynamicSharedMemorySize,
                         (int)FUSED_SMEM);
    dim3 g(L_ / TILE_L, B_);
    fused_kernel<<<g, THREADS, FUSED_SMEM>>>(times, features, mask, usample, W, bias, out);
}

// round 15
// speedup vs baseline: 1.7500x; 1.3333x over previous
#include <cuda_runtime.h>
#include <cuda_bf16.h>
#include <cstdint>

#define B_ 32
#define L_ 2048
#define S_ 8
#define HALO 8
#define OUT_ROWS 18424
#define TILE_L 72
#define ROWS_T 80
#define NTILES 29            // ceil(2048/72)
#define THREADS 320          // 10 warps
#define BSTR 72              // bf16 matrix row stride (elements) -> 144B, conflict-free frags
#define ROWP 68              // Ps/Qs row stride in floats

// dynamic smem layout (bytes):
// phase 1: A_hi@0(11520) A_lo@11520(11520) W_hi@23040(9216) W_lo@32256(9216)
//          BB_hi@41472(9216) BB_lo@50688(9216)  -> total 59904
// phase 2 alias: Ps@0 (80*68*4=21760), Qs@21760 -> 43520
#define OFF_A_HI 0
#define OFF_A_LO 11520
#define OFF_W_HI 23040
#define OFF_W_LO 32256
#define OFF_BB_HI 41472
#define OFF_BB_LO 50688
#define OFF_PS 0
#define OFF_QS 21760
#define DYN_SMEM 59904

// m16n8k16 bf16 mma with f32 accumulate (sm_80+ PTX -> HMMA on sm_100)
static __device__ __forceinline__ void mma16816(float* d, uint32_t a0, uint32_t a1,
                                                uint32_t a2, uint32_t a3,
                                                uint32_t b0, uint32_t b1) {
    asm volatile(
        "mma.sync.aligned.m16n8k16.row.col.f32.bf16.bf16.f32 "
        "{%0,%1,%2,%3}, {%4,%5,%6,%7}, {%8,%9}, {%0,%1,%2,%3};"
        : "+f"(d[0]), "+f"(d[1]), "+f"(d[2]), "+f"(d[3])
        : "r"(a0), "r"(a1), "r"(a2), "r"(a3), "r"(b0), "r"(b1));
}

// bf16 hi/lo split of a float pair, packed bf16x2 (first element in low half)
static __device__ __forceinline__ void split2(float a, float b, uint32_t& h, uint32_t& l) {
    __nv_bfloat16 ah = __float2bfloat16(a), bh = __float2bfloat16(b);
    __nv_bfloat16 al = __float2bfloat16(a - __bfloat162float(ah));
    __nv_bfloat16 bl = __float2bfloat16(b - __bfloat162float(bh));
    h = (uint32_t)*(uint16_t*)&ah | ((uint32_t)*(uint16_t*)&bh << 16);
    l = (uint32_t)*(uint16_t*)&al | ((uint32_t)*(uint16_t*)&bl << 16);
}
static __device__ __forceinline__ void split8(const float* f, uint4& h, uint4& l) {
    split2(f[0], f[1], h.x, l.x);
    split2(f[2], f[3], h.y, l.y);
    split2(f[4], f[5], h.z, l.z);
    split2(f[6], f[7], h.w, l.w);
}

// non_pad_mask dtype probe (lengths >= L/2 so mask[0,0..1] true).
static __device__ __forceinline__ int mask_kind(const unsigned char* m) {
    unsigned char b0 = m[0], b1 = m[1];
    if (b0 == 1 && b1 != 0) return 0;
    if (b0 == 1) return 1;
    return 2;
}

__global__ __launch_bounds__(THREADS) void fused_kernel(const float* __restrict__ times,
                                                        const float* __restrict__ F,
                                                        const void* __restrict__ maskp,
                                                        const float* __restrict__ usample,
                                                        const float* __restrict__ W,
                                                        const float* __restrict__ bias,
                                                        float* __restrict__ out) {
    extern __shared__ __align__(16) char smem[];
    __shared__ float ts[ROWS_T + 2];
    __shared__ float vsf[ROWS_T + 2];
    __shared__ float us[S_];

    int tid = threadIdx.x, wid = tid >> 5, lane = tid & 31;
    int b = blockIdx.y;
    int tileStart = blockIdx.x * TILE_L;
    const float* gF = F + (size_t)b * L_ * 64;

    // ---- phase 0: convert inputs to bf16 hi/lo in smem ----
    // A: 80 rows x 64 c.  thread = (row = tid>>2, quarter q = tid&3 -> 16 cols)
    {
        int row = tid >> 2, q = tid & 3;
        int gl = tileStart - HALO + row;
        bool ok = (gl >= 0 && gl < L_);
        const float* fr = gF + (size_t)(ok ? gl : 0) * 64 + q * 16;
#pragma unroll
        for (int j = 0; j < 2; j++) {
            float f8[8];
            if (ok) {
                *(float4*)&f8[0] = ((const float4*)fr)[j * 2];
                *(float4*)&f8[4] = ((const float4*)fr)[j * 2 + 1];
            } else {
#pragma unroll
                for (int z = 0; z < 8; z++) f8[z] = 0.f;
            }
            uint4 h, l;
            split8(f8, h, l);
            uint32_t off = (uint32_t)(row * BSTR + q * 16 + j * 8) * 2;
            *(uint4*)(smem + OFF_A_HI + off) = h;
            *(uint4*)(smem + OFF_A_LO + off) = l;
        }
    }
    if (tid < 256) {
        int row = tid >> 2, q = tid & 3;
        // W[o][c] (row-major, already B-fragment layout for .col)
#pragma unroll
        for (int j = 0; j < 2; j++) {
            int c0 = q * 16 + j * 8;
            float f8[8];
            *(float4*)&f8[0] = *(const float4*)&W[row * 64 + c0];
            *(float4*)&f8[4] = *(const float4*)&W[row * 64 + c0 + 4];
            uint4 h, l;
            split8(f8, h, l);
            uint32_t off = (uint32_t)(row * BSTR + c0) * 2;
            *(uint4*)(smem + OFF_W_HI + off) = h;
            *(uint4*)(smem + OFF_W_LO + off) = l;
        }
        // BB[o][c] = bias[c][o] (transpose gather)
#pragma unroll
        for (int j = 0; j < 2; j++) {
            int c0 = q * 16 + j * 8;
            float f8[8];
#pragma unroll
            for (int c = 0; c < 8; c++) f8[c] = bias[(c0 + c) * 64 + row];
            uint4 h, l;
            split8(f8, h, l);
            uint32_t off = (uint32_t)(row * BSTR + c0) * 2;
            *(uint4*)(smem + OFF_BB_HI + off) = h;
            *(uint4*)(smem + OFF_BB_LO + off) = l;
        }
    }
    if (tid < ROWS_T + 1) {
        int kind = mask_kind((const unsigned char*)maskp);
        int gl = tileStart - HALO + tid;
        float t = 0.f, v = 0.f;
        if (gl >= 0 && gl < L_) {
            int mi = b * L_ + gl;
            t = times[mi];
            bool mv;
            if (kind == 0)      mv = ((const unsigned char*)maskp)[mi] != 0;
            else if (kind == 1) mv = ((const int*)maskp)[mi] != 0;
            else                mv = ((const float*)maskp)[mi] != 0.f;
            v = mv ? 1.f : 0.f;
        }
        ts[tid] = t;
        vsf[tid] = v;
    }
    if (tid < S_) us[tid] = usample[tid];
    __syncthreads();

    // ---- phase 1: tensor-core GEMM. warp = (gemm = wid>=5, m-tile = wid%5) ----
    // acc[nt][0..3]: nt-th n8-tile, rows (m0+g, m0+g+8), cols (nt*8 + t4*2, +1)
    int gemm = wid >= 5;
    int mtile = gemm ? wid - 5 : wid;
    int m0 = mtile * 16;
    int g = lane >> 2, t4 = lane & 3;

    float acc[8][4];
#pragma unroll
    for (int nt = 0; nt < 8; nt++)
#pragma unroll
        for (int z = 0; z < 4; z++) acc[nt][z] = 0.f;

    const char* Ahi = smem + OFF_A_HI;
    const char* Alo = smem + OFF_A_LO;
    const char* Bhi = smem + (gemm ? OFF_BB_HI : OFF_W_HI);
    const char* Blo = smem + (gemm ? OFF_BB_LO : OFF_W_LO);

#pragma unroll
    for (int split = 0; split < 3; split++) {
        const char* Ab = (split < 2) ? Ahi : Alo;
        const char* Bb = (split == 1) ? Blo : Bhi;
#pragma unroll
        for (int k4 = 0; k4 < 4; k4++) {
            int k = k4 * 16 + t4 * 2;
            uint32_t a0 = *(const uint32_t*)(Ab + ((m0 + g) * BSTR + k) * 2);
            uint32_t a1 = *(const uint32_t*)(Ab + ((m0 + g + 8) * BSTR + k) * 2);
            uint32_t a2 = *(const uint32_t*)(Ab + ((m0 + g) * BSTR + k + 8) * 2);
            uint32_t a3 = *(const uint32_t*)(Ab + ((m0 + g + 8) * BSTR + k + 8) * 2);
#pragma unroll
            for (int nt = 0; nt < 8; nt++) {
                uint32_t b0 = *(const uint32_t*)(Bb + ((nt * 8 + g) * BSTR + k) * 2);
                uint32_t b1 = *(const uint32_t*)(Bb + ((nt * 8 + g) * BSTR + k + 8) * 2);
                mma16816(acc[nt], a0, a1, a2, a3, b0, b1);
            }
        }
    }
    __syncthreads();   // all smem GEMM-input reads done -> safe to alias Ps/Qs

    // masked writeback: Ps = m_j * P, Qs = m_j * Q
    {
        float* Dst = (float*)(smem + (gemm ? OFF_QS : OFF_PS));
        float mr0 = vsf[m0 + g], mr8 = vsf[m0 + g + 8];
#pragma unroll
        for (int nt = 0; nt < 8; nt++) {
            int col = nt * 8 + t4 * 2;
            *(float2*)&Dst[(m0 + g) * ROWP + col] =
                make_float2(acc[nt][0] * mr0, acc[nt][1] * mr0);
            *(float2*)&Dst[(m0 + g + 8) * ROWP + col] =
                make_float2(acc[nt][2] * mr8, acc[nt][3] * mr8);
        }
    }
    __syncthreads();

    // ---- phase 2: sliding-window combine over 72 l's ----
    // real[l] = m_l*(t_l*A + E),   A = sum_{j=l-8..l-1} mP_j,  E = sum (mQ_j - t_j*mP_j)
    // sim[l]  = m_l*(t_l*An + En), An/En = window advanced to j=l-7..l (8 taps)
    // sum_lin = m_l*An.  320 threads = 16 o4-lanes x 20 chunks (12x4 + 8x3 = 72).
    {
        const float* Ps = (const float*)(smem + OFF_PS);
        const float* Qs = (const float*)(smem + OFF_QS);
        int o4 = (tid & 15) * 4;
        int ck = tid >> 4;                       // 0..19
        int l0  = ck < 12 ? ck * 4 : 48 + (ck - 12) * 3;
        int len = ck < 12 ? 4 : 3;

        float4 A = make_float4(0.f, 0.f, 0.f, 0.f);
        float4 E = make_float4(0.f, 0.f, 0.f, 0.f);
#pragma unroll
        for (int i = 0; i < 8; i++) {            // init window rows l0..l0+7
            int r = l0 + i;
            float4 p = *(const float4*)&Ps[r * ROWP + o4];
            float4 q = *(const float4*)&Qs[r * ROWP + o4];
            float t = ts[r];
            A.x += p.x; A.y += p.y; A.z += p.z; A.w += p.w;
            E.x += fmaf(-t, p.x, q.x); E.y += fmaf(-t, p.y, q.y);
            E.z += fmaf(-t, p.z, q.z); E.w += fmaf(-t, p.w, q.w);
        }

#pragma unroll
        for (int i = 0; i < 4; i++) {
            if (i >= len) break;
            int ll = l0 + i;
            int l = tileStart + ll;
            if (l >= L_) break;
            float tl = ts[ll + HALO];
            float m  = vsf[ll + HALO];

            float4 pn = *(const float4*)&Ps[(ll + HALO) * ROWP + o4];   // new tap j=l
            float4 qn = *(const float4*)&Qs[(ll + HALO) * ROWP + o4];
            float4 po = *(const float4*)&Ps[ll * ROWP + o4];            // old tap j=l-8
            float4 qo = *(const float4*)&Qs[ll * ROWP + o4];
            float to = ts[ll];

            float4 An, En;
            An.x = A.x + pn.x - po.x; An.y = A.y + pn.y - po.y;
            An.z = A.z + pn.z - po.z; An.w = A.w + pn.w - po.w;
            En.x = fmaf(to, po.x, fmaf(-tl, pn.x, E.x + qn.x) - qo.x);
            En.y = fmaf(to, po.y, fmaf(-tl, pn.y, E.y + qn.y) - qo.y);
            En.z = fmaf(to, po.z, fmaf(-tl, pn.z, E.z + qn.z) - qo.z);
            En.w = fmaf(to, po.w, fmaf(-tl, pn.w, E.w + qn.w) - qo.w);

            float4 re, sbv, sl;
            re.x = m * fmaf(tl, A.x, E.x);    re.y = m * fmaf(tl, A.y, E.y);
            re.z = m * fmaf(tl, A.z, E.z);    re.w = m * fmaf(tl, A.w, E.w);
            sbv.x = m * fmaf(tl, An.x, En.x); sbv.y = m * fmaf(tl, An.y, En.y);
            sbv.z = m * fmaf(tl, An.z, En.z); sbv.w = m * fmaf(tl, An.w, En.w);
            sl.x = m * An.x; sl.y = m * An.y; sl.z = m * An.z; sl.w = m * An.w;

            float* ob = out + ((size_t)b * OUT_ROWS + (size_t)l * 9) * 64 + o4;
            *(float4*)ob = re;

            if (l < L_ - 1) {
                float udt = (m != 0.f && vsf[ll + HALO + 1] != 0.f)
                                ? (ts[ll + HALO + 1] - tl) : 0.f;
#pragma unroll
                for (int s = 0; s < S_; s++) {
                    float f = udt * us[s];
                    float4 v = make_float4(fmaf(f, sl.x, sbv.x), fmaf(f, sl.y, sbv.y),
                                           fmaf(f, sl.z, sbv.z), fmaf(f, sl.w, sbv.w));
                    *(float4*)(ob + (s + 1) * 64) = v;
                }
            }
            A = An;
            E = En;
        }
    }
}

extern "C" void kernel_launch(void* const* d_in, const int* in_sizes, int n_in,
                              void* d_out, int out_size) {
    const float* times    = (const float*)d_in[0];
    const float* features = (const float*)d_in[1];
    const void*  mask     = d_in[2];
    const float* usample  = (const float*)d_in[3];
    const float* W        = (const float*)d_in[4];
    const float* bias     = (const float*)d_in[5];
    float* out = (float*)d_out;

    cudaFuncSetAttribute(fused_kernel, cudaFuncAttributeMaxDynamicSharedMemorySize,
                         DYN_SMEM);
    dim3 g(NTILES, B_);
    fused_kernel<<<g, THREADS, DYN_SMEM>>>(times, features, mask, usample, W, bias, out);
}

// round 16
// speedup vs baseline: 1.9091x; 1.0909x over previous
#include <cuda_runtime.h>
#include <cuda_bf16.h>
#include <cstdint>

#define B_ 32
#define L_ 2048
#define S_ 8
#define HALO 8
#define OUT_ROWS 18424
#define TILE_L 56
#define ROWS_T 64            // TILE_L + HALO, 4 m16 tiles
#define NTILES 37            // ceil(2048/56)
#define THREADS 256          // 8 warps: 4 P + 4 Q
#define BSTR 72              // bf16 matrix row stride (elements) -> 144B, conflict-free frags
#define ROWP 68              // Ps/Qs row stride in floats

// dynamic smem layout (bytes):
// phase 1: A_hi@0(9216) A_lo@9216 W_hi@18432 W_lo@27648 BB_hi@36864 BB_lo@46080 -> 55296
// phase 2 alias: Ps@0 (64*68*4=17408), Qs@17408 -> 34816
#define OFF_A_HI 0
#define OFF_A_LO 9216
#define OFF_W_HI 18432
#define OFF_W_LO 27648
#define OFF_BB_HI 36864
#define OFF_BB_LO 46080
#define OFF_PS 0
#define OFF_QS 17408
#define DYN_SMEM 55296

// m16n8k16 bf16 mma with f32 accumulate (sm_80+ PTX -> HMMA on sm_100)
static __device__ __forceinline__ void mma16816(float* d, uint32_t a0, uint32_t a1,
                                                uint32_t a2, uint32_t a3,
                                                uint32_t b0, uint32_t b1) {
    asm volatile(
        "mma.sync.aligned.m16n8k16.row.col.f32.bf16.bf16.f32 "
        "{%0,%1,%2,%3}, {%4,%5,%6,%7}, {%8,%9}, {%0,%1,%2,%3};"
        : "+f"(d[0]), "+f"(d[1]), "+f"(d[2]), "+f"(d[3])
        : "r"(a0), "r"(a1), "r"(a2), "r"(a3), "r"(b0), "r"(b1));
}

// bf16 hi/lo split of a float pair, packed bf16x2 (first element in low half)
static __device__ __forceinline__ void split2(float a, float b, uint32_t& h, uint32_t& l) {
    __nv_bfloat16 ah = __float2bfloat16(a), bh = __float2bfloat16(b);
    __nv_bfloat16 al = __float2bfloat16(a - __bfloat162float(ah));
    __nv_bfloat16 bl = __float2bfloat16(b - __bfloat162float(bh));
    h = (uint32_t)*(uint16_t*)&ah | ((uint32_t)*(uint16_t*)&bh << 16);
    l = (uint32_t)*(uint16_t*)&al | ((uint32_t)*(uint16_t*)&bl << 16);
}
static __device__ __forceinline__ void split4(const float* f, uint2& h, uint2& l) {
    split2(f[0], f[1], h.x, l.x);
    split2(f[2], f[3], h.y, l.y);
}

// non_pad_mask dtype probe (lengths >= L/2 so mask[0,0..1] true).
static __device__ __forceinline__ int mask_kind(const unsigned char* m) {
    unsigned char b0 = m[0], b1 = m[1];
    if (b0 == 1 && b1 != 0) return 0;
    if (b0 == 1) return 1;
    return 2;
}

__global__ __launch_bounds__(THREADS, 3) void fused_kernel(const float* __restrict__ times,
                                                           const float* __restrict__ F,
                                                           const void* __restrict__ maskp,
                                                           const float* __restrict__ usample,
                                                           const float* __restrict__ W,
                                                           const float* __restrict__ bias,
                                                           float* __restrict__ out) {
    extern __shared__ __align__(16) char smem[];
    __shared__ float ts[ROWS_T + 2];
    __shared__ float vsf[ROWS_T + 2];
    __shared__ float us[S_];

    int tid = threadIdx.x, wid = tid >> 5, lane = tid & 31;
    int b = blockIdx.y;
    int tileStart = blockIdx.x * TILE_L;
    const float* gF = F + (size_t)b * L_ * 64;

    // ---- phase 0: convert inputs to bf16 hi/lo in smem ----
    // A: 64 rows x 64 c. thread = (row = tid>>2, quarter q = tid&3 -> 16 cols), 4-col steps
    {
        int row = tid >> 2, q = tid & 3;
        int gl = tileStart - HALO + row;
        bool ok = (gl >= 0 && gl < L_);
        const float* fr = gF + (size_t)(ok ? gl : 0) * 64 + q * 16;
#pragma unroll
        for (int j = 0; j < 4; j++) {
            float f4v[4];
            if (ok) *(float4*)f4v = ((const float4*)fr)[j];
            else { f4v[0] = f4v[1] = f4v[2] = f4v[3] = 0.f; }
            uint2 h, l;
            split4(f4v, h, l);
            uint32_t off = (uint32_t)(row * BSTR + q * 16 + j * 4) * 2;
            *(uint2*)(smem + OFF_A_HI + off) = h;
            *(uint2*)(smem + OFF_A_LO + off) = l;
        }
        // W[o][c] row-major (already B-fragment layout for .col)
#pragma unroll
        for (int j = 0; j < 4; j++) {
            float f4v[4];
            *(float4*)f4v = *(const float4*)&W[row * 64 + q * 16 + j * 4];
            uint2 h, l;
            split4(f4v, h, l);
            uint32_t off = (uint32_t)(row * BSTR + q * 16 + j * 4) * 2;
            *(uint2*)(smem + OFF_W_HI + off) = h;
            *(uint2*)(smem + OFF_W_LO + off) = l;
        }
        // BB[o][c] = bias[c][o] (transpose gather)
#pragma unroll
        for (int j = 0; j < 4; j++) {
            int c0 = q * 16 + j * 4;
            float f4v[4];
#pragma unroll
            for (int c = 0; c < 4; c++) f4v[c] = bias[(c0 + c) * 64 + row];
            uint2 h, l;
            split4(f4v, h, l);
            uint32_t off = (uint32_t)(row * BSTR + c0) * 2;
            *(uint2*)(smem + OFF_BB_HI + off) = h;
            *(uint2*)(smem + OFF_BB_LO + off) = l;
        }
    }
    if (tid < ROWS_T + 1) {
        int kind = mask_kind((const unsigned char*)maskp);
        int gl = tileStart - HALO + tid;
        float t = 0.f, v = 0.f;
        if (gl >= 0 && gl < L_) {
            int mi = b * L_ + gl;
            t = times[mi];
            bool mv;
            if (kind == 0)      mv = ((const unsigned char*)maskp)[mi] != 0;
            else if (kind == 1) mv = ((const int*)maskp)[mi] != 0;
            else                mv = ((const float*)maskp)[mi] != 0.f;
            v = mv ? 1.f : 0.f;
        }
        ts[tid] = t;
        vsf[tid] = v;
    }
    if (tid < S_) us[tid] = usample[tid];
    __syncthreads();

    // ---- phase 1: tensor-core GEMM. warp = (gemm = wid>=4, m-tile = wid&3) ----
    int gemm = wid >> 2;
    int m0 = (wid & 3) * 16;
    int g = lane >> 2, t4 = lane & 3;

    float acc[8][4];
#pragma unroll
    for (int nt = 0; nt < 8; nt++)
#pragma unroll
        for (int z = 0; z < 4; z++) acc[nt][z] = 0.f;

    const char* Ahi = smem + OFF_A_HI;
    const char* Alo = smem + OFF_A_LO;
    const char* Bhi = smem + (gemm ? OFF_BB_HI : OFF_W_HI);
    const char* Blo = smem + (gemm ? OFF_BB_LO : OFF_W_LO);

#pragma unroll
    for (int split = 0; split < 3; split++) {
        const char* Ab = (split < 2) ? Ahi : Alo;
        const char* Bb = (split == 1) ? Blo : Bhi;
#pragma unroll
        for (int k4 = 0; k4 < 4; k4++) {
            int k = k4 * 16 + t4 * 2;
            uint32_t a0 = *(const uint32_t*)(Ab + ((m0 + g) * BSTR + k) * 2);
            uint32_t a1 = *(const uint32_t*)(Ab + ((m0 + g + 8) * BSTR + k) * 2);
            uint32_t a2 = *(const uint32_t*)(Ab + ((m0 + g) * BSTR + k + 8) * 2);
            uint32_t a3 = *(const uint32_t*)(Ab + ((m0 + g + 8) * BSTR + k + 8) * 2);
#pragma unroll
            for (int nt = 0; nt < 8; nt++) {
                uint32_t b0 = *(const uint32_t*)(Bb + ((nt * 8 + g) * BSTR + k) * 2);
                uint32_t b1 = *(const uint32_t*)(Bb + ((nt * 8 + g) * BSTR + k + 8) * 2);
                mma16816(acc[nt], a0, a1, a2, a3, b0, b1);
            }
        }
    }
    __syncthreads();   // all smem GEMM-input reads done -> safe to alias Ps/Qs

    // masked writeback: Ps = m_j * P, Qs = m_j * Q
    {
        float* Dst = (float*)(smem + (gemm ? OFF_QS : OFF_PS));
        float mr0 = vsf[m0 + g], mr8 = vsf[m0 + g + 8];
#pragma unroll
        for (int nt = 0; nt < 8; nt++) {
            int col = nt * 8 + t4 * 2;
            *(float2*)&Dst[(m0 + g) * ROWP + col] =
                make_float2(acc[nt][0] * mr0, acc[nt][1] * mr0);
            *(float2*)&Dst[(m0 + g + 8) * ROWP + col] =
                make_float2(acc[nt][2] * mr8, acc[nt][3] * mr8);
        }
    }
    __syncthreads();

    // ---- phase 2: sliding-window combine over 56 l's ----
    // real[l] = m_l*(t_l*A + E),   A = sum_{j=l-8..l-1} mP_j,  E = sum (mQ_j - t_j*mP_j)
    // sim[l]  = m_l*(t_l*An + En), An/En = window advanced to j=l-7..l (8 taps)
    // sum_lin = m_l*An.  256 threads = 16 o4-lanes x 16 chunks (8x4 + 8x3 = 56).
    {
        const float* Ps = (const float*)(smem + OFF_PS);
        const float* Qs = (const float*)(smem + OFF_QS);
        int o4 = (tid & 15) * 4;
        int ck = tid >> 4;                       // 0..15
        int l0  = ck < 8 ? ck * 4 : 32 + (ck - 8) * 3;
        int len = ck < 8 ? 4 : 3;

        float4 A = make_float4(0.f, 0.f, 0.f, 0.f);
        float4 E = make_float4(0.f, 0.f, 0.f, 0.f);
#pragma unroll
        for (int i = 0; i < 8; i++) {            // init window rows l0..l0+7
            int r = l0 + i;
            float4 p = *(const float4*)&Ps[r * ROWP + o4];
            float4 q = *(const float4*)&Qs[r * ROWP + o4];
            float t = ts[r];
            A.x += p.x; A.y += p.y; A.z += p.z; A.w += p.w;
            E.x += fmaf(-t, p.x, q.x); E.y += fmaf(-t, p.y, q.y);
            E.z += fmaf(-t, p.z, q.z); E.w += fmaf(-t, p.w, q.w);
        }

#pragma unroll
        for (int i = 0; i < 4; i++) {
            if (i >= len) break;
            int ll = l0 + i;
            int l = tileStart + ll;
            if (l >= L_) break;
            float tl = ts[ll + HALO];
            float m  = vsf[ll + HALO];

            float4 pn = *(const float4*)&Ps[(ll + HALO) * ROWP + o4];   // new tap j=l
            float4 qn = *(const float4*)&Qs[(ll + HALO) * ROWP + o4];
            float4 po = *(const float4*)&Ps[ll * ROWP + o4];            // old tap j=l-8
            float4 qo = *(const float4*)&Qs[ll * ROWP + o4];
            float to = ts[ll];

            float4 An, En;
            An.x = A.x + pn.x - po.x; An.y = A.y + pn.y - po.y;
            An.z = A.z + pn.z - po.z; An.w = A.w + pn.w - po.w;
            En.x = fmaf(to, po.x, fmaf(-tl, pn.x, E.x + qn.x) - qo.x);
            En.y = fmaf(to, po.y, fmaf(-tl, pn.y, E.y + qn.y) - qo.y);
            En.z = fmaf(to, po.z, fmaf(-tl, pn.z, E.z + qn.z) - qo.z);
            En.w = fmaf(to, po.w, fmaf(-tl, pn.w, E.w + qn.w) - qo.w);

            float4 re, sbv, sl;
            re.x = m * fmaf(tl, A.x, E.x);    re.y = m * fmaf(tl, A.y, E.y);
            re.z = m * fmaf(tl, A.z, E.z);    re.w = m * fmaf(tl, A.w, E.w);
            sbv.x = m * fmaf(tl, An.x, En.x); sbv.y = m * fmaf(tl, An.y, En.y);
            sbv.z = m * fmaf(tl, An.z, En.z); sbv.w = m * fmaf(tl, An.w, En.w);
            sl.x = m * An.x; sl.y = m * An.y; sl.z = m * An.z; sl.w = m * An.w;

            float* ob = out + ((size_t)b * OUT_ROWS + (size_t)l * 9) * 64 + o4;
            *(float4*)ob = re;

            if (l < L_ - 1) {
                float udt = (m != 0.f && vsf[ll + HALO + 1] != 0.f)
                                ? (ts[ll + HALO + 1] - tl) : 0.f;
#pragma unroll
                for (int s = 0; s < S_; s++) {
                    float f = udt * us[s];
                    float4 v = make_float4(fmaf(f, sl.x, sbv.x), fmaf(f, sl.y, sbv.y),
                                           fmaf(f, sl.z, sbv.z), fmaf(f, sl.w, sbv.w));
                    *(float4*)(ob + (s + 1) * 64) = v;
                }
            }
            A = An;
            E = En;
        }
    }
}

extern "C" void kernel_launch(void* const* d_in, const int* in_sizes, int n_in,
                              void* d_out, int out_size) {
    const float* times    = (const float*)d_in[0];
    const float* features = (const float*)d_in[1];
    const void*  mask     = d_in[2];
    const float* usample  = (const float*)d_in[3];
    const float* W        = (const float*)d_in[4];
    const float* bias     = (const float*)d_in[5];
    float* out = (float*)d_out;

    cudaFuncSetAttribute(fused_kernel, cudaFuncAttributeMaxDynamicSharedMemorySize,
                         DYN_SMEM);
    dim3 g(NTILES, B_);
    fused_kernel<<<g, THREADS, DYN_SMEM>>>(times, features, mask, usample, W, bias, out);
}